// round 1
// baseline (speedup 1.0000x reference)
#include <cuda_runtime.h>
#include <cuda_bf16.h>
#include <math.h>

// Problem constants
#define T_TOK 8192
#define D_DIM 768
#define W_MAX 32

// Scratch for precomputed query projection Q_all = emb @ Wq^T + bq  (25 MB)
__device__ float g_Qall[(size_t)T_TOK * D_DIM];

// ---------------------------------------------------------------------------
// Kernel 1: Q_all[t,e] = sum_d emb[t,d] * Wq[e,d] + bq[e]
// Classic smem-tiled SGEMM, NT layout (both operands K-contiguous).
// BM=128, BN=128, BK=16, 256 threads, 8x8 per thread.
// ---------------------------------------------------------------------------
#define BM 128
#define BN 128
#define BK 16
#define TM 8
#define TN 8

__global__ __launch_bounds__(256, 2)
void qproj_kernel(const float* __restrict__ A,   // emb [T, D]
                  const float* __restrict__ B,   // Wq  [D, D]  (rows = e, cols = d)
                  const float* __restrict__ bias)
{
    __shared__ float As[BK][BM];
    __shared__ float Bs[BK][BN];

    const int K = D_DIM;
    const int tid = threadIdx.x;
    const int tx = tid & 15;          // 0..15  (col group)
    const int ty = tid >> 4;          // 0..15  (row group)

    const int rowBase = blockIdx.y * BM;   // over t (8192/128 = 64)
    const int colBase = blockIdx.x * BN;   // over e (768/128 = 6)

    float acc[TM][TN];
    #pragma unroll
    for (int i = 0; i < TM; i++)
        #pragma unroll
        for (int j = 0; j < TN; j++) acc[i][j] = 0.f;

    for (int kt = 0; kt < K; kt += BK) {
        // Load A tile (128 x 16) as 512 float4, 2 per thread, store transposed
        #pragma unroll
        for (int l = 0; l < 2; l++) {
            int idx = tid + l * 256;           // 0..511
            int row = idx >> 2;                // 0..127
            int kv  = idx & 3;                 // float4 index within 16 k's
            float4 a4 = *reinterpret_cast<const float4*>(
                &A[(size_t)(rowBase + row) * K + kt + kv * 4]);
            As[kv * 4 + 0][row] = a4.x;
            As[kv * 4 + 1][row] = a4.y;
            As[kv * 4 + 2][row] = a4.z;
            As[kv * 4 + 3][row] = a4.w;
        }
        // Load B tile (128 x 16) same way
        #pragma unroll
        for (int l = 0; l < 2; l++) {
            int idx = tid + l * 256;
            int row = idx >> 2;
            int kv  = idx & 3;
            float4 b4 = *reinterpret_cast<const float4*>(
                &B[(size_t)(colBase + row) * K + kt + kv * 4]);
            Bs[kv * 4 + 0][row] = b4.x;
            Bs[kv * 4 + 1][row] = b4.y;
            Bs[kv * 4 + 2][row] = b4.z;
            Bs[kv * 4 + 3][row] = b4.w;
        }
        __syncthreads();

        #pragma unroll
        for (int kk = 0; kk < BK; kk++) {
            float af[TM], bf[TN];
            #pragma unroll
            for (int i = 0; i < TM; i++) af[i] = As[kk][ty * TM + i];
            #pragma unroll
            for (int j = 0; j < TN; j++) bf[j] = Bs[kk][tx * TN + j];
            #pragma unroll
            for (int i = 0; i < TM; i++)
                #pragma unroll
                for (int j = 0; j < TN; j++)
                    acc[i][j] = fmaf(af[i], bf[j], acc[i][j]);
        }
        __syncthreads();
    }

    // Epilogue: add bias, write Q_all
    #pragma unroll
    for (int i = 0; i < TM; i++) {
        int r = rowBase + ty * TM + i;
        #pragma unroll
        for (int j = 0; j < TN; j++) {
            int c = colBase + tx * TN + j;
            g_Qall[(size_t)r * D_DIM + c] = acc[i][j] + bias[c];
        }
    }
}

// ---------------------------------------------------------------------------
// Kernel 2: per-span attention. One block (256 threads / 8 warps) per span.
//   E  = emb rows [start .. start+L-1]  (contiguous!) staged in dyn smem
//   Q  = g_Qall rows (same positions), read from L2 per warp
//   S[q,k] = Q[q]·E[k];  softmax over k;  c[k] = sum_q w[q,k];  out = c @ E
// ---------------------------------------------------------------------------
extern __shared__ float sE[];   // [L][768], up to 32*768 floats = 96 KB

__global__ __launch_bounds__(256, 2)
void span_attn_kernel(const float* __restrict__ emb,
                      const int*   __restrict__ spans,
                      float*       __restrict__ out)
{
    __shared__ float csum[W_MAX];

    const int n    = blockIdx.x;
    const int tid  = threadIdx.x;
    const int lane = tid & 31;
    const int warp = tid >> 5;

    const int start = spans[2 * n];
    const int end   = spans[2 * n + 1];
    const int L     = end - start + 1;      // 1..32

    if (tid < W_MAX) csum[tid] = 0.f;

    // Stage E: L contiguous rows of 768 floats -> L*192 float4
    {
        const float4* src = reinterpret_cast<const float4*>(emb + (size_t)start * D_DIM);
        float4* dst = reinterpret_cast<float4*>(sE);
        const int total = L * (D_DIM / 4);
        for (int i = tid; i < total; i += 256) dst[i] = src[i];
    }
    __syncthreads();

    // Each warp handles q rows warp, warp+8, ...
    for (int q = warp; q < L; q += 8) {
        const float* Qrow = g_Qall + (size_t)(start + q) * D_DIM;
        float qreg[24];
        #pragma unroll
        for (int i = 0; i < 24; i++) qreg[i] = Qrow[lane + 32 * i];

        float myS = -INFINITY;   // lane k holds s[k]
        for (int k = 0; k < L; k++) {
            const float* Er = sE + k * D_DIM;
            float s = 0.f;
            #pragma unroll
            for (int i = 0; i < 24; i++) s = fmaf(qreg[i], Er[lane + 32 * i], s);
            #pragma unroll
            for (int o = 16; o > 0; o >>= 1) s += __shfl_xor_sync(0xffffffffu, s, o);
            if (lane == k) myS = s;
        }
        // warp softmax over lanes 0..L-1
        float m = myS;
        #pragma unroll
        for (int o = 16; o > 0; o >>= 1) m = fmaxf(m, __shfl_xor_sync(0xffffffffu, m, o));
        float e = (lane < L) ? __expf(myS - m) : 0.f;
        float sum = e;
        #pragma unroll
        for (int o = 16; o > 0; o >>= 1) sum += __shfl_xor_sync(0xffffffffu, sum, o);
        float w = e / sum;
        if (lane < L) atomicAdd(&csum[lane], w);
    }
    __syncthreads();

    // out[n,:] = c @ E
    float* od = out + (size_t)n * D_DIM;
    for (int d = tid; d < D_DIM; d += 256) {
        float acc = 0.f;
        for (int k = 0; k < L; k++) acc = fmaf(csum[k], sE[k * D_DIM + d], acc);
        od[d] = acc;
    }
}

// ---------------------------------------------------------------------------
extern "C" void kernel_launch(void* const* d_in, const int* in_sizes, int n_in,
                              void* d_out, int out_size)
{
    const float* emb   = (const float*)d_in[0];   // [T, D]
    const int*   spans = (const int*)  d_in[1];   // [N, 2]
    const float* Wq    = (const float*)d_in[2];   // [D, D]
    const float* bq    = (const float*)d_in[3];   // [D]
    float* out = (float*)d_out;                   // [N, D]

    const int n_spans = in_sizes[1] / 2;

    // Kernel 1: query projection for all tokens
    dim3 g1(D_DIM / BN, T_TOK / BM);
    qproj_kernel<<<g1, 256>>>(emb, Wq, bq);

    // Kernel 2: per-span attention (96 KB dynamic smem)
    const int smem = W_MAX * D_DIM * (int)sizeof(float);
    cudaFuncSetAttribute(span_attn_kernel,
                         cudaFuncAttributeMaxDynamicSharedMemorySize, smem);
    span_attn_kernel<<<n_spans, 256, smem>>>(emb, spans, out);
}

// round 2
// speedup vs baseline: 1.0450x; 1.0450x over previous
#include <cuda_runtime.h>
#include <cuda_bf16.h>
#include <math.h>

#define T_TOK 8192
#define D_DIM 768
#define W_MAX 32

// Scratch for precomputed query projection Q_all = emb @ Wq^T + bq  (25 MB)
__device__ float g_Qall[(size_t)T_TOK * D_DIM];

// ---------------------------------------------------------------------------
// Kernel 1: Q_all[t,e] = sum_d emb[t,d] * Wq[e,d] + bq[e]
// Double-buffered SGEMM, BM=64, BN=128, BK=16, 256 threads, 4x8 per thread.
// grid = (6, 128) = 768 blocks -> ~3 CTA/SM -> good wave quantization.
// ---------------------------------------------------------------------------
#define BM 64
#define BN 128
#define BK 16
#define TM 4
#define TN 8

__global__ __launch_bounds__(256, 3)
void qproj_kernel(const float* __restrict__ A,   // emb [T, D]
                  const float* __restrict__ B,   // Wq  [D, D] (row e, col d)
                  const float* __restrict__ bias)
{
    __shared__ float As[2][BK][BM];   // 2 * 4 KB
    __shared__ float Bs[2][BK][BN];   // 2 * 8 KB

    const int K = D_DIM;
    const int tid = threadIdx.x;
    const int tx = tid & 15;          // 0..15 (col group, 8 each)
    const int ty = tid >> 4;          // 0..15 (row group, 4 each)

    const int rowBase = blockIdx.y * BM;   // over t
    const int colBase = blockIdx.x * BN;   // over e

    // load indices: A tile 64x16 = 256 float4 (1/thread), B tile 128x16 = 512 (2/thread)
    const int arow = tid >> 2;        // 0..63
    const int akv  = tid & 3;         // float4 index in k
    const int brow0 = tid >> 2;       // first B row
    const int bkv   = tid & 3;

    const float* Aptr = A + (size_t)(rowBase + arow) * K + akv * 4;
    const float* Bptr0 = B + (size_t)(colBase + brow0) * K + bkv * 4;
    const float* Bptr1 = B + (size_t)(colBase + brow0 + 64) * K + bkv * 4;

    // preload tile 0
    {
        float4 a4 = *reinterpret_cast<const float4*>(Aptr);
        As[0][akv*4+0][arow] = a4.x; As[0][akv*4+1][arow] = a4.y;
        As[0][akv*4+2][arow] = a4.z; As[0][akv*4+3][arow] = a4.w;
        float4 b4 = *reinterpret_cast<const float4*>(Bptr0);
        Bs[0][bkv*4+0][brow0] = b4.x; Bs[0][bkv*4+1][brow0] = b4.y;
        Bs[0][bkv*4+2][brow0] = b4.z; Bs[0][bkv*4+3][brow0] = b4.w;
        float4 c4 = *reinterpret_cast<const float4*>(Bptr1);
        Bs[0][bkv*4+0][brow0+64] = c4.x; Bs[0][bkv*4+1][brow0+64] = c4.y;
        Bs[0][bkv*4+2][brow0+64] = c4.z; Bs[0][bkv*4+3][brow0+64] = c4.w;
    }
    __syncthreads();

    float acc[TM][TN];
    #pragma unroll
    for (int i = 0; i < TM; i++)
        #pragma unroll
        for (int j = 0; j < TN; j++) acc[i][j] = 0.f;

    const int nTiles = K / BK;   // 48
    int buf = 0;

    for (int t = 0; t < nTiles; t++) {
        float4 fa, fb, fc;
        const bool more = (t + 1 < nTiles);
        if (more) {
            int koff = (t + 1) * BK;
            fa = *reinterpret_cast<const float4*>(Aptr + koff);
            fb = *reinterpret_cast<const float4*>(Bptr0 + koff);
            fc = *reinterpret_cast<const float4*>(Bptr1 + koff);
        }

        #pragma unroll
        for (int kk = 0; kk < BK; kk++) {
            float4 a0 = *reinterpret_cast<const float4*>(&As[buf][kk][ty * TM]);
            float4 b0 = *reinterpret_cast<const float4*>(&Bs[buf][kk][tx * TN]);
            float4 b1 = *reinterpret_cast<const float4*>(&Bs[buf][kk][tx * TN + 4]);
            float af[TM] = {a0.x, a0.y, a0.z, a0.w};
            float bf[TN] = {b0.x, b0.y, b0.z, b0.w, b1.x, b1.y, b1.z, b1.w};
            #pragma unroll
            for (int i = 0; i < TM; i++)
                #pragma unroll
                for (int j = 0; j < TN; j++)
                    acc[i][j] = fmaf(af[i], bf[j], acc[i][j]);
        }

        if (more) {
            int nb = buf ^ 1;
            As[nb][akv*4+0][arow] = fa.x; As[nb][akv*4+1][arow] = fa.y;
            As[nb][akv*4+2][arow] = fa.z; As[nb][akv*4+3][arow] = fa.w;
            Bs[nb][bkv*4+0][brow0] = fb.x; Bs[nb][bkv*4+1][brow0] = fb.y;
            Bs[nb][bkv*4+2][brow0] = fb.z; Bs[nb][bkv*4+3][brow0] = fb.w;
            Bs[nb][bkv*4+0][brow0+64] = fc.x; Bs[nb][bkv*4+1][brow0+64] = fc.y;
            Bs[nb][bkv*4+2][brow0+64] = fc.z; Bs[nb][bkv*4+3][brow0+64] = fc.w;
            __syncthreads();
            buf = nb;
        }
    }

    #pragma unroll
    for (int i = 0; i < TM; i++) {
        int r = rowBase + ty * TM + i;
        #pragma unroll
        for (int j = 0; j < TN; j++) {
            int c = colBase + tx * TN + j;
            g_Qall[(size_t)r * D_DIM + c] = acc[i][j] + bias[c];
        }
    }
}

// ---------------------------------------------------------------------------
// Kernel 2: per-span attention. One block (256 threads / 8 warps) per span.
// Phase 1: warp w owns query rows 4w..4w+3 held in registers; loops k,
//          each E float4 from smem feeds 16 FMAs; 9-shfl 4-way fold gives
//          all 4 dot products; raw scores -> smem sS.
// Phase 2: softmax per q row from sS, column-sum into csum.
// Phase 3: out = csum @ E.
// ---------------------------------------------------------------------------
extern __shared__ float sE[];   // [32][768] fp32, 96 KB

__global__ __launch_bounds__(256, 2)
void span_attn_kernel(const float* __restrict__ emb,
                      const int*   __restrict__ spans,
                      float*       __restrict__ out)
{
    __shared__ float sS[W_MAX][W_MAX + 1];  // raw scores, padded
    __shared__ float csum[W_MAX];

    const int n    = blockIdx.x;
    const int tid  = threadIdx.x;
    const int lane = tid & 31;
    const int warp = tid >> 5;

    const int start = spans[2 * n];
    const int end   = spans[2 * n + 1];
    const int L     = end - start + 1;      // 1..32

    if (tid < W_MAX) csum[tid] = 0.f;

    // --- Load this warp's 4 query rows into registers (before the barrier,
    //     so the global-load latency overlaps E staging by other warps).
    const int q0 = 4 * warp;
    const bool active = (q0 < L);
    float4 qr[4][6];
    if (active) {
        #pragma unroll
        for (int j = 0; j < 4; j++) {
            const float4* Qrow = reinterpret_cast<const float4*>(
                g_Qall + (size_t)(start + q0 + j) * D_DIM);
            #pragma unroll
            for (int i = 0; i < 6; i++) qr[j][i] = Qrow[lane + 32 * i];
        }
    }

    // --- Stage E: L contiguous rows of 768 floats
    {
        const float4* src = reinterpret_cast<const float4*>(emb + (size_t)start * D_DIM);
        float4* dst = reinterpret_cast<float4*>(sE);
        const int total = L * (D_DIM / 4);
        for (int i = tid; i < total; i += 256) dst[i] = src[i];
    }
    __syncthreads();

    // --- Phase 1: scores
    if (active) {
        const float4* sE4 = reinterpret_cast<const float4*>(sE);
        for (int k = 0; k < L; k++) {
            const float4* Ek = sE4 + k * 192;
            float s0 = 0.f, s1 = 0.f, s2 = 0.f, s3 = 0.f;
            #pragma unroll
            for (int i = 0; i < 6; i++) {
                float4 e = Ek[lane + 32 * i];
                s0 = fmaf(qr[0][i].x, e.x, s0); s0 = fmaf(qr[0][i].y, e.y, s0);
                s0 = fmaf(qr[0][i].z, e.z, s0); s0 = fmaf(qr[0][i].w, e.w, s0);
                s1 = fmaf(qr[1][i].x, e.x, s1); s1 = fmaf(qr[1][i].y, e.y, s1);
                s1 = fmaf(qr[1][i].z, e.z, s1); s1 = fmaf(qr[1][i].w, e.w, s1);
                s2 = fmaf(qr[2][i].x, e.x, s2); s2 = fmaf(qr[2][i].y, e.y, s2);
                s2 = fmaf(qr[2][i].z, e.z, s2); s2 = fmaf(qr[2][i].w, e.w, s2);
                s3 = fmaf(qr[3][i].x, e.x, s3); s3 = fmaf(qr[3][i].y, e.y, s3);
                s3 = fmaf(qr[3][i].z, e.z, s3); s3 = fmaf(qr[3][i].w, e.w, s3);
            }
            // 4-way fold: 9 shfls reduce all 4 dots; 8-lane groups end with sums
            float u0 = s0 + __shfl_xor_sync(0xffffffffu, s0, 16);
            float u1 = s1 + __shfl_xor_sync(0xffffffffu, s1, 16);
            float u2 = s2 + __shfl_xor_sync(0xffffffffu, s2, 16);
            float u3 = s3 + __shfl_xor_sync(0xffffffffu, s3, 16);
            float z0 = (lane & 16) ? u2 : u0;
            float z1 = (lane & 16) ? u3 : u1;
            z0 += __shfl_xor_sync(0xffffffffu, z0, 8);
            z1 += __shfl_xor_sync(0xffffffffu, z1, 8);
            float y = (lane & 8) ? z1 : z0;
            y += __shfl_xor_sync(0xffffffffu, y, 4);
            y += __shfl_xor_sync(0xffffffffu, y, 2);
            y += __shfl_xor_sync(0xffffffffu, y, 1);
            // lanes 0,8,16,24 hold dots for q0+0..q0+3
            const int j = lane >> 3;
            if ((lane & 7) == 0 && q0 + j < L) sS[q0 + j][k] = y;
        }
    }
    __syncthreads();

    // --- Phase 2: softmax per q row, accumulate column sums
    for (int q = warp; q < L; q += 8) {
        float s = (lane < L) ? sS[q][lane] : -INFINITY;
        float m = s;
        #pragma unroll
        for (int o = 16; o > 0; o >>= 1) m = fmaxf(m, __shfl_xor_sync(0xffffffffu, m, o));
        float e = (lane < L) ? __expf(s - m) : 0.f;
        float sum = e;
        #pragma unroll
        for (int o = 16; o > 0; o >>= 1) sum += __shfl_xor_sync(0xffffffffu, sum, o);
        float w = e / sum;
        if (lane < L) atomicAdd(&csum[lane], w);
    }
    __syncthreads();

    // --- Phase 3: out[n,:] = csum @ E
    float* od = out + (size_t)n * D_DIM;
    for (int d = tid; d < D_DIM; d += 256) {
        float acc = 0.f;
        for (int k = 0; k < L; k++) acc = fmaf(csum[k], sE[k * D_DIM + d], acc);
        od[d] = acc;
    }
}

// ---------------------------------------------------------------------------
extern "C" void kernel_launch(void* const* d_in, const int* in_sizes, int n_in,
                              void* d_out, int out_size)
{
    const float* emb   = (const float*)d_in[0];   // [T, D]
    const int*   spans = (const int*)  d_in[1];   // [N, 2]
    const float* Wq    = (const float*)d_in[2];   // [D, D]
    const float* bq    = (const float*)d_in[3];   // [D]
    float* out = (float*)d_out;                   // [N, D]

    const int n_spans = in_sizes[1] / 2;

    dim3 g1(D_DIM / BN, T_TOK / BM);
    qproj_kernel<<<g1, 256>>>(emb, Wq, bq);

    const int smem = W_MAX * D_DIM * (int)sizeof(float);
    cudaFuncSetAttribute(span_attn_kernel,
                         cudaFuncAttributeMaxDynamicSharedMemorySize, smem);
    span_attn_kernel<<<n_spans, 256, smem>>>(emb, spans, out);
}

// round 3
// speedup vs baseline: 1.1958x; 1.1443x over previous
#include <cuda_runtime.h>
#include <cuda_bf16.h>
#include <math.h>

#define T_TOK 8192
#define D_DIM 768
#define W_MAX 32
#define N_SPAN_MAX 10000
#define NBUCK 8

// Scratch
__device__ float g_Qall[(size_t)T_TOK * D_DIM];
__device__ int   g_cnt[NBUCK];
__device__ int   g_list[NBUCK][N_SPAN_MAX];

// ---------------------------------------------------------------------------
// Kernel 0: bin spans by length into 8 buckets (L in [4b+1, 4b+4]).
// Single block; smem atomics give unique slots.
// ---------------------------------------------------------------------------
__global__ void bin_kernel(const int* __restrict__ spans, int n)
{
    __shared__ int scnt[NBUCK];
    if (threadIdx.x < NBUCK) scnt[threadIdx.x] = 0;
    __syncthreads();
    for (int i = threadIdx.x; i < n; i += blockDim.x) {
        int L = spans[2 * i + 1] - spans[2 * i] + 1;
        int b = (L - 1) >> 2;
        int p = atomicAdd(&scnt[b], 1);
        g_list[b][p] = i;
    }
    __syncthreads();
    if (threadIdx.x < NBUCK) g_cnt[threadIdx.x] = scnt[threadIdx.x];
}

// ---------------------------------------------------------------------------
// Kernel 1: Q_all[t,e] = sum_d emb[t,d] * Wq[e,d] + bq[e]   (R0 version, ~fp32 peak)
// ---------------------------------------------------------------------------
#define BM 128
#define BN 128
#define BK 16
#define TM 8
#define TN 8

__global__ __launch_bounds__(256, 2)
void qproj_kernel(const float* __restrict__ A,
                  const float* __restrict__ B,
                  const float* __restrict__ bias)
{
    __shared__ float As[BK][BM];
    __shared__ float Bs[BK][BN];

    const int K = D_DIM;
    const int tid = threadIdx.x;
    const int tx = tid & 15;
    const int ty = tid >> 4;

    const int rowBase = blockIdx.y * BM;
    const int colBase = blockIdx.x * BN;

    float acc[TM][TN];
    #pragma unroll
    for (int i = 0; i < TM; i++)
        #pragma unroll
        for (int j = 0; j < TN; j++) acc[i][j] = 0.f;

    for (int kt = 0; kt < K; kt += BK) {
        #pragma unroll
        for (int l = 0; l < 2; l++) {
            int idx = tid + l * 256;
            int row = idx >> 2;
            int kv  = idx & 3;
            float4 a4 = *reinterpret_cast<const float4*>(
                &A[(size_t)(rowBase + row) * K + kt + kv * 4]);
            As[kv * 4 + 0][row] = a4.x;
            As[kv * 4 + 1][row] = a4.y;
            As[kv * 4 + 2][row] = a4.z;
            As[kv * 4 + 3][row] = a4.w;
        }
        #pragma unroll
        for (int l = 0; l < 2; l++) {
            int idx = tid + l * 256;
            int row = idx >> 2;
            int kv  = idx & 3;
            float4 b4 = *reinterpret_cast<const float4*>(
                &B[(size_t)(colBase + row) * K + kt + kv * 4]);
            Bs[kv * 4 + 0][row] = b4.x;
            Bs[kv * 4 + 1][row] = b4.y;
            Bs[kv * 4 + 2][row] = b4.z;
            Bs[kv * 4 + 3][row] = b4.w;
        }
        __syncthreads();

        #pragma unroll
        for (int kk = 0; kk < BK; kk++) {
            float af[TM], bf[TN];
            #pragma unroll
            for (int i = 0; i < TM; i++) af[i] = As[kk][ty * TM + i];
            #pragma unroll
            for (int j = 0; j < TN; j++) bf[j] = Bs[kk][tx * TN + j];
            #pragma unroll
            for (int i = 0; i < TM; i++)
                #pragma unroll
                for (int j = 0; j < TN; j++)
                    acc[i][j] = fmaf(af[i], bf[j], acc[i][j]);
        }
        __syncthreads();
    }

    #pragma unroll
    for (int i = 0; i < TM; i++) {
        int r = rowBase + ty * TM + i;
        #pragma unroll
        for (int j = 0; j < TN; j++) {
            int c = colBase + tx * TN + j;
            g_Qall[(size_t)r * D_DIM + c] = acc[i][j] + bias[c];
        }
    }
}

// ---------------------------------------------------------------------------
// Kernel 2 (templated on bucket): per-span attention.
// Bucket B handles L in [4B+1, 4B+4]; block has NW=B+1 warps; each warp owns
// 4 query rows (registers), computes scores vs E (smem), then does its own
// rows' softmax (warp-local, no block barrier) and atomicAdds column sums.
// ---------------------------------------------------------------------------
template<int B>
__global__ void __launch_bounds__(32 * (B + 1))
span_attn_t(const float* __restrict__ emb,
            const int*   __restrict__ spans,
            float*       __restrict__ out)
{
    constexpr int NW   = B + 1;
    constexpr int LMAX = 4 * NW;
    constexpr int NTHR = 32 * NW;

    extern __shared__ float sE[];               // [L][768]
    __shared__ float sS[LMAX][LMAX + 1];        // raw scores
    __shared__ float csum[LMAX];

    const int bid = blockIdx.x;
    if (bid >= g_cnt[B]) return;
    const int n = g_list[B][bid];

    const int tid  = threadIdx.x;
    const int lane = tid & 31;
    const int warp = tid >> 5;

    const int start = spans[2 * n];
    const int end   = spans[2 * n + 1];
    const int L     = end - start + 1;          // in [4B+1, 4B+4]

    if (tid < LMAX) csum[tid] = 0.f;

    // Load this warp's 4 query rows into registers (overlaps E staging).
    const int q0 = 4 * warp;                    // q0 <= LMAX-4 <= L-1 always
    float4 qr[4][6];
    #pragma unroll
    for (int j = 0; j < 4; j++) {
        const float4* Qrow = reinterpret_cast<const float4*>(
            g_Qall + (size_t)(start + q0 + j) * D_DIM);
        #pragma unroll
        for (int i = 0; i < 6; i++) qr[j][i] = Qrow[lane + 32 * i];
    }

    // Stage E: L contiguous rows of 768 floats
    {
        const float4* src = reinterpret_cast<const float4*>(emb + (size_t)start * D_DIM);
        float4* dst = reinterpret_cast<float4*>(sE);
        const int total = L * (D_DIM / 4);
        for (int i = tid; i < total; i += NTHR) dst[i] = src[i];
    }
    __syncthreads();

    // Scores: 4 q-rows per warp, loop k. 96 FMA + 9-shfl fold per k.
    {
        const float4* sE4 = reinterpret_cast<const float4*>(sE);
        #pragma unroll 2
        for (int k = 0; k < L; k++) {
            const float4* Ek = sE4 + k * 192;
            float s0 = 0.f, s1 = 0.f, s2 = 0.f, s3 = 0.f;
            #pragma unroll
            for (int i = 0; i < 6; i++) {
                float4 e = Ek[lane + 32 * i];
                s0 = fmaf(qr[0][i].x, e.x, s0); s0 = fmaf(qr[0][i].y, e.y, s0);
                s0 = fmaf(qr[0][i].z, e.z, s0); s0 = fmaf(qr[0][i].w, e.w, s0);
                s1 = fmaf(qr[1][i].x, e.x, s1); s1 = fmaf(qr[1][i].y, e.y, s1);
                s1 = fmaf(qr[1][i].z, e.z, s1); s1 = fmaf(qr[1][i].w, e.w, s1);
                s2 = fmaf(qr[2][i].x, e.x, s2); s2 = fmaf(qr[2][i].y, e.y, s2);
                s2 = fmaf(qr[2][i].z, e.z, s2); s2 = fmaf(qr[2][i].w, e.w, s2);
                s3 = fmaf(qr[3][i].x, e.x, s3); s3 = fmaf(qr[3][i].y, e.y, s3);
                s3 = fmaf(qr[3][i].z, e.z, s3); s3 = fmaf(qr[3][i].w, e.w, s3);
            }
            float u0 = s0 + __shfl_xor_sync(0xffffffffu, s0, 16);
            float u1 = s1 + __shfl_xor_sync(0xffffffffu, s1, 16);
            float u2 = s2 + __shfl_xor_sync(0xffffffffu, s2, 16);
            float u3 = s3 + __shfl_xor_sync(0xffffffffu, s3, 16);
            float z0 = (lane & 16) ? u2 : u0;
            float z1 = (lane & 16) ? u3 : u1;
            z0 += __shfl_xor_sync(0xffffffffu, z0, 8);
            z1 += __shfl_xor_sync(0xffffffffu, z1, 8);
            float y = (lane & 8) ? z1 : z0;
            y += __shfl_xor_sync(0xffffffffu, y, 4);
            y += __shfl_xor_sync(0xffffffffu, y, 2);
            y += __shfl_xor_sync(0xffffffffu, y, 1);
            const int j = lane >> 3;
            if ((lane & 7) == 0 && q0 + j < L) sS[q0 + j][k] = y;
        }
    }
    __syncwarp();

    // Per-warp softmax of its own rows + column-sum accumulation.
    #pragma unroll
    for (int j = 0; j < 4; j++) {
        const int q = q0 + j;
        if (q < L) {
            float s = (lane < L) ? sS[q][lane] : -INFINITY;
            float m = s;
            #pragma unroll
            for (int o = 16; o > 0; o >>= 1) m = fmaxf(m, __shfl_xor_sync(0xffffffffu, m, o));
            float e = (lane < L) ? __expf(s - m) : 0.f;
            float sum = e;
            #pragma unroll
            for (int o = 16; o > 0; o >>= 1) sum += __shfl_xor_sync(0xffffffffu, sum, o);
            float w = e / sum;
            if (lane < L) atomicAdd(&csum[lane], w);
        }
    }
    __syncthreads();

    // out[n,:] = csum @ E
    float* od = out + (size_t)n * D_DIM;
    for (int d = tid; d < D_DIM; d += NTHR) {
        float acc = 0.f;
        #pragma unroll 4
        for (int k = 0; k < L; k++) acc = fmaf(csum[k], sE[k * D_DIM + d], acc);
        od[d] = acc;
    }
}

// ---------------------------------------------------------------------------
extern "C" void kernel_launch(void* const* d_in, const int* in_sizes, int n_in,
                              void* d_out, int out_size)
{
    const float* emb   = (const float*)d_in[0];
    const int*   spans = (const int*)  d_in[1];
    const float* Wq    = (const float*)d_in[2];
    const float* bq    = (const float*)d_in[3];
    float* out = (float*)d_out;

    const int n_spans = in_sizes[1] / 2;

    bin_kernel<<<1, 256>>>(spans, n_spans);

    dim3 g1(D_DIM / BN, T_TOK / BM);
    qproj_kernel<<<g1, 256>>>(emb, Wq, bq);

    // 8 bucketed span kernels; fixed worst-case grids (graph-capturable),
    // early-exit on blockIdx >= count.
    #define LAUNCH_BUCKET(b)                                                        \
        do {                                                                        \
            const int smem = 4 * ((b) + 1) * D_DIM * (int)sizeof(float);            \
            cudaFuncSetAttribute(span_attn_t<(b)>,                                  \
                                 cudaFuncAttributeMaxDynamicSharedMemorySize, smem);\
            span_attn_t<(b)><<<n_spans, 32 * ((b) + 1), smem>>>(emb, spans, out);   \
        } while (0)

    LAUNCH_BUCKET(0);
    LAUNCH_BUCKET(1);
    LAUNCH_BUCKET(2);
    LAUNCH_BUCKET(3);
    LAUNCH_BUCKET(4);
    LAUNCH_BUCKET(5);
    LAUNCH_BUCKET(6);
    LAUNCH_BUCKET(7);
    #undef LAUNCH_BUCKET
}

// round 4
// speedup vs baseline: 1.2716x; 1.0634x over previous
#include <cuda_runtime.h>
#include <cuda_bf16.h>
#include <math.h>

#define T_TOK 8192
#define D_DIM 768
#define W_MAX 32
#define N_SPAN_MAX 10000
#define NCLS 32

// Scratch
__device__ float g_Qall[(size_t)T_TOK * D_DIM];
__device__ int   g_sorted[N_SPAN_MAX];   // span ids grouped by exact L
__device__ int   g_cbase[NCLS + 1];      // span-list base per class
__device__ int   g_bbase[NCLS + 1];      // block base per class

__host__ __device__ __forceinline__ int cls_w(int c)    { return ((c + 1) + 3) >> 2; }  // ceil(L/4), L=c+1
__host__ __device__ __forceinline__ int cls_pack(int c) { return 8 / cls_w(c); }

// ---------------------------------------------------------------------------
// Kernel 0: counting-sort spans by exact length; build class/block tables.
// ---------------------------------------------------------------------------
__global__ void bin_sort_kernel(const int* __restrict__ spans, int n)
{
    __shared__ int scnt[NCLS];
    __shared__ int scur[NCLS];
    __shared__ int sbase[NCLS + 1];

    const int tid = threadIdx.x;
    if (tid < NCLS) scnt[tid] = 0;
    __syncthreads();

    for (int i = tid; i < n; i += blockDim.x) {
        int L = spans[2 * i + 1] - spans[2 * i] + 1;
        atomicAdd(&scnt[L - 1], 1);
    }
    __syncthreads();

    if (tid == 0) {
        int acc = 0, bacc = 0;
        for (int c = 0; c < NCLS; c++) {
            sbase[c] = acc;
            g_cbase[c] = acc;
            g_bbase[c] = bacc;
            int cnt = scnt[c];
            acc  += cnt;
            int pack = cls_pack(c);
            bacc += (cnt + pack - 1) / pack;
        }
        sbase[NCLS] = acc;
        g_cbase[NCLS] = acc;
        g_bbase[NCLS] = bacc;
    }
    if (tid < NCLS) scur[tid] = 0;
    __syncthreads();

    for (int i = tid; i < n; i += blockDim.x) {
        int L = spans[2 * i + 1] - spans[2 * i] + 1;
        int c = L - 1;
        int p = atomicAdd(&scur[c], 1);
        g_sorted[sbase[c] + p] = i;
    }
}

// ---------------------------------------------------------------------------
// Kernel 1: Q_all[t,e] = sum_d emb[t,d] * Wq[e,d] + bq[e]   (~fp32 FFMA peak)
// ---------------------------------------------------------------------------
#define BM 128
#define BN 128
#define BK 16
#define TM 8
#define TN 8

__global__ __launch_bounds__(256, 2)
void qproj_kernel(const float* __restrict__ A,
                  const float* __restrict__ B,
                  const float* __restrict__ bias)
{
    __shared__ float As[BK][BM];
    __shared__ float Bs[BK][BN];

    const int K = D_DIM;
    const int tid = threadIdx.x;
    const int tx = tid & 15;
    const int ty = tid >> 4;

    const int rowBase = blockIdx.y * BM;
    const int colBase = blockIdx.x * BN;

    float acc[TM][TN];
    #pragma unroll
    for (int i = 0; i < TM; i++)
        #pragma unroll
        for (int j = 0; j < TN; j++) acc[i][j] = 0.f;

    for (int kt = 0; kt < K; kt += BK) {
        #pragma unroll
        for (int l = 0; l < 2; l++) {
            int idx = tid + l * 256;
            int row = idx >> 2;
            int kv  = idx & 3;
            float4 a4 = *reinterpret_cast<const float4*>(
                &A[(size_t)(rowBase + row) * K + kt + kv * 4]);
            As[kv * 4 + 0][row] = a4.x;
            As[kv * 4 + 1][row] = a4.y;
            As[kv * 4 + 2][row] = a4.z;
            As[kv * 4 + 3][row] = a4.w;
        }
        #pragma unroll
        for (int l = 0; l < 2; l++) {
            int idx = tid + l * 256;
            int row = idx >> 2;
            int kv  = idx & 3;
            float4 b4 = *reinterpret_cast<const float4*>(
                &B[(size_t)(colBase + row) * K + kt + kv * 4]);
            Bs[kv * 4 + 0][row] = b4.x;
            Bs[kv * 4 + 1][row] = b4.y;
            Bs[kv * 4 + 2][row] = b4.z;
            Bs[kv * 4 + 3][row] = b4.w;
        }
        __syncthreads();

        #pragma unroll
        for (int kk = 0; kk < BK; kk++) {
            float af[TM], bf[TN];
            #pragma unroll
            for (int i = 0; i < TM; i++) af[i] = As[kk][ty * TM + i];
            #pragma unroll
            for (int j = 0; j < TN; j++) bf[j] = Bs[kk][tx * TN + j];
            #pragma unroll
            for (int i = 0; i < TM; i++)
                #pragma unroll
                for (int j = 0; j < TN; j++)
                    acc[i][j] = fmaf(af[i], bf[j], acc[i][j]);
        }
        __syncthreads();
    }

    #pragma unroll
    for (int i = 0; i < TM; i++) {
        int r = rowBase + ty * TM + i;
        #pragma unroll
        for (int j = 0; j < TN; j++) {
            int c = colBase + tx * TN + j;
            g_Qall[(size_t)r * D_DIM + c] = acc[i][j] + bias[c];
        }
    }
}

// ---------------------------------------------------------------------------
// Kernel 2: packed span attention. One 256-thread block serves `pack` spans
// of the same exact length L. Warp -> (slot, q-group of 4 rows).
// ---------------------------------------------------------------------------
extern __shared__ float sE[];   // pack * L * 768 floats (<= 96 KB)

__global__ __launch_bounds__(256, 2)
void span_attn_kernel(const float* __restrict__ emb,
                      const int*   __restrict__ spans,
                      float*       __restrict__ out)
{
    __shared__ int   sBB[NCLS + 1];
    __shared__ int   sid[8];       // span ids for slots
    __shared__ int   sst[8];       // span starts
    __shared__ float sS[1088];     // scores, per-slot stride 4w*(L+1)
    __shared__ float csum[8][W_MAX];

    const int tid  = threadIdx.x;
    const int lane = tid & 31;
    const int warp = tid >> 5;

    if (tid <= NCLS) sBB[tid] = g_bbase[tid];
    __syncthreads();

    const int b = blockIdx.x;
    if (b >= sBB[NCLS]) return;

    // class lookup (monotone table, <=32 steps)
    int c = 0;
    while (b >= sBB[c + 1]) c++;

    const int L    = c + 1;
    const int w    = cls_w(c);         // warp-tasks per span
    const int pack = 8 / w;            // spans per block
    const int idxc = b - sBB[c];

    const int cbase = g_cbase[c];
    const int ccnt  = g_cbase[c + 1] - cbase;
    const int sbase = idxc * pack;
    const int nslot = min(pack, ccnt - sbase);

    if (tid < nslot) {
        int nid = g_sorted[cbase + sbase + tid];
        sid[tid] = nid;
        sst[tid] = spans[2 * nid];
    }
    {   // zero csum
        float* cz = &csum[0][0];
        if (tid < 8 * W_MAX) cz[tid] = 0.f;
    }
    __syncthreads();

    // --- per-warp task ---
    const int slot   = warp / w;
    const int qg     = warp - slot * w;
    const bool active = (slot < nslot);
    const int q0 = 4 * qg;
    const int sstride = 4 * w * (L + 1);          // per-slot score stride
    const int myStart = active ? sst[slot] : 0;

    // Load 4 query rows into registers (overlaps E staging by other threads)
    float4 qr[4][6];
    if (active) {
        #pragma unroll
        for (int j = 0; j < 4; j++) {
            int qi = q0 + j; if (qi > L - 1) qi = L - 1;   // clamp (dup rows unused)
            const float4* Qrow = reinterpret_cast<const float4*>(
                g_Qall + (size_t)(myStart + qi) * D_DIM);
            #pragma unroll
            for (int i = 0; i < 6; i++) qr[j][i] = Qrow[lane + 32 * i];
        }
    }

    // --- stage E for all slots ---
    for (int s = 0; s < nslot; s++) {
        const float4* src = reinterpret_cast<const float4*>(emb + (size_t)sst[s] * D_DIM);
        float4* dst = reinterpret_cast<float4*>(sE + (size_t)s * L * D_DIM);
        const int total = L * (D_DIM / 4);
        for (int i = tid; i < total; i += 256) dst[i] = src[i];
    }
    __syncthreads();

    // --- scores ---
    if (active) {
        const float4* sE4 = reinterpret_cast<const float4*>(sE + (size_t)slot * L * D_DIM);
        float* sSlot = sS + slot * sstride;
        #pragma unroll 2
        for (int k = 0; k < L; k++) {
            const float4* Ek = sE4 + k * 192;
            float s0 = 0.f, s1 = 0.f, s2 = 0.f, s3 = 0.f;
            #pragma unroll
            for (int i = 0; i < 6; i++) {
                float4 e = Ek[lane + 32 * i];
                s0 = fmaf(qr[0][i].x, e.x, s0); s0 = fmaf(qr[0][i].y, e.y, s0);
                s0 = fmaf(qr[0][i].z, e.z, s0); s0 = fmaf(qr[0][i].w, e.w, s0);
                s1 = fmaf(qr[1][i].x, e.x, s1); s1 = fmaf(qr[1][i].y, e.y, s1);
                s1 = fmaf(qr[1][i].z, e.z, s1); s1 = fmaf(qr[1][i].w, e.w, s1);
                s2 = fmaf(qr[2][i].x, e.x, s2); s2 = fmaf(qr[2][i].y, e.y, s2);
                s2 = fmaf(qr[2][i].z, e.z, s2); s2 = fmaf(qr[2][i].w, e.w, s2);
                s3 = fmaf(qr[3][i].x, e.x, s3); s3 = fmaf(qr[3][i].y, e.y, s3);
                s3 = fmaf(qr[3][i].z, e.z, s3); s3 = fmaf(qr[3][i].w, e.w, s3);
            }
            float u0 = s0 + __shfl_xor_sync(0xffffffffu, s0, 16);
            float u1 = s1 + __shfl_xor_sync(0xffffffffu, s1, 16);
            float u2 = s2 + __shfl_xor_sync(0xffffffffu, s2, 16);
            float u3 = s3 + __shfl_xor_sync(0xffffffffu, s3, 16);
            float z0 = (lane & 16) ? u2 : u0;
            float z1 = (lane & 16) ? u3 : u1;
            z0 += __shfl_xor_sync(0xffffffffu, z0, 8);
            z1 += __shfl_xor_sync(0xffffffffu, z1, 8);
            float y = (lane & 8) ? z1 : z0;
            y += __shfl_xor_sync(0xffffffffu, y, 4);
            y += __shfl_xor_sync(0xffffffffu, y, 2);
            y += __shfl_xor_sync(0xffffffffu, y, 1);
            const int j = lane >> 3;
            const int q = q0 + j;
            if ((lane & 7) == 0 && q < L) sSlot[q * (L + 1) + k] = y;
        }
        __syncwarp();

        // --- per-warp softmax of its own rows + column-sum ---
        #pragma unroll
        for (int j = 0; j < 4; j++) {
            const int q = q0 + j;
            if (q < L) {
                float s = (lane < L) ? sSlot[q * (L + 1) + lane] : -INFINITY;
                float m = s;
                #pragma unroll
                for (int o = 16; o > 0; o >>= 1) m = fmaxf(m, __shfl_xor_sync(0xffffffffu, m, o));
                float e = (lane < L) ? __expf(s - m) : 0.f;
                float sum = e;
                #pragma unroll
                for (int o = 16; o > 0; o >>= 1) sum += __shfl_xor_sync(0xffffffffu, sum, o);
                float ww = e / sum;
                if (lane < L) atomicAdd(&csum[slot][lane], ww);
            }
        }
    }
    __syncthreads();

    // --- epilogue: out[n_s,:] = csum_s @ E_s ---
    for (int s = 0; s < nslot; s++) {
        const float* Eslot = sE + (size_t)s * L * D_DIM;
        float* od = out + (size_t)sid[s] * D_DIM;
        for (int d = tid; d < D_DIM; d += 256) {
            float acc = 0.f;
            #pragma unroll 4
            for (int k = 0; k < L; k++) acc = fmaf(csum[s][k], Eslot[k * D_DIM + d], acc);
            od[d] = acc;
        }
    }
}

// ---------------------------------------------------------------------------
extern "C" void kernel_launch(void* const* d_in, const int* in_sizes, int n_in,
                              void* d_out, int out_size)
{
    const float* emb   = (const float*)d_in[0];
    const int*   spans = (const int*)  d_in[1];
    const float* Wq    = (const float*)d_in[2];
    const float* bq    = (const float*)d_in[3];
    float* out = (float*)d_out;

    const int n_spans = in_sizes[1] / 2;

    bin_sort_kernel<<<1, 1024>>>(spans, n_spans);

    dim3 g1(D_DIM / BN, T_TOK / BM);
    qproj_kernel<<<g1, 256>>>(emb, Wq, bq);

    const int smem = W_MAX * D_DIM * (int)sizeof(float);   // 96 KB worst case
    cudaFuncSetAttribute(span_attn_kernel,
                         cudaFuncAttributeMaxDynamicSharedMemorySize, smem);
    span_attn_kernel<<<n_spans, 256, smem>>>(emb, spans, out);
}

// round 9
// speedup vs baseline: 1.8130x; 1.4258x over previous
#include <cuda_runtime.h>
#include <cuda_bf16.h>
#include <math.h>

#define T_TOK 8192
#define D_DIM 768
#define W_MAX 32
#define BANDW 64          // offsets o = j - i + 31, o in [0,62], padded to 64

// Scratch
__device__ float g_Qall[(size_t)T_TOK * D_DIM];          // 25 MB
__device__ float g_M[(size_t)T_TOK * BANDW];             // 2 MB banded scores

// ---------------------------------------------------------------------------
// Kernel 1: Q_all[t,e] = sum_d emb[t,d] * Wq[e,d] + bq[e]   (~fp32 FFMA peak)
// ---------------------------------------------------------------------------
#define BM 128
#define BN 128
#define BK 16
#define TM 8
#define TN 8

__global__ __launch_bounds__(256, 2)
void qproj_kernel(const float* __restrict__ A,
                  const float* __restrict__ B,
                  const float* __restrict__ bias)
{
    __shared__ float As[BK][BM];
    __shared__ float Bs[BK][BN];

    const int K = D_DIM;
    const int tid = threadIdx.x;
    const int tx = tid & 15;
    const int ty = tid >> 4;

    const int rowBase = blockIdx.y * BM;
    const int colBase = blockIdx.x * BN;

    float acc[TM][TN];
    #pragma unroll
    for (int i = 0; i < TM; i++)
        #pragma unroll
        for (int j = 0; j < TN; j++) acc[i][j] = 0.f;

    for (int kt = 0; kt < K; kt += BK) {
        #pragma unroll
        for (int l = 0; l < 2; l++) {
            int idx = tid + l * 256;
            int row = idx >> 2;
            int kv  = idx & 3;
            float4 a4 = *reinterpret_cast<const float4*>(
                &A[(size_t)(rowBase + row) * K + kt + kv * 4]);
            As[kv * 4 + 0][row] = a4.x;
            As[kv * 4 + 1][row] = a4.y;
            As[kv * 4 + 2][row] = a4.z;
            As[kv * 4 + 3][row] = a4.w;
        }
        #pragma unroll
        for (int l = 0; l < 2; l++) {
            int idx = tid + l * 256;
            int row = idx >> 2;
            int kv  = idx & 3;
            float4 b4 = *reinterpret_cast<const float4*>(
                &B[(size_t)(colBase + row) * K + kt + kv * 4]);
            Bs[kv * 4 + 0][row] = b4.x;
            Bs[kv * 4 + 1][row] = b4.y;
            Bs[kv * 4 + 2][row] = b4.z;
            Bs[kv * 4 + 3][row] = b4.w;
        }
        __syncthreads();

        #pragma unroll
        for (int kk = 0; kk < BK; kk++) {
            float af[TM], bf[TN];
            #pragma unroll
            for (int i = 0; i < TM; i++) af[i] = As[kk][ty * TM + i];
            #pragma unroll
            for (int j = 0; j < TN; j++) bf[j] = Bs[kk][tx * TN + j];
            #pragma unroll
            for (int i = 0; i < TM; i++)
                #pragma unroll
                for (int j = 0; j < TN; j++)
                    acc[i][j] = fmaf(af[i], bf[j], acc[i][j]);
        }
        __syncthreads();
    }

    #pragma unroll
    for (int i = 0; i < TM; i++) {
        int r = rowBase + ty * TM + i;
        #pragma unroll
        for (int j = 0; j < TN; j++) {
            int c = colBase + tx * TN + j;
            g_Qall[(size_t)r * D_DIM + c] = acc[i][j] + bias[c];
        }
    }
}

// ---------------------------------------------------------------------------
// Kernel 2: banded scores M[i][o] = Qall[i] . emb[i + o - 31],  o in [0,63).
// TI=64 tokens per block (grid 128). emb rows needed: [i0-31, i0+95) -> 128.
// KC=64 k-chunk; 16x16 threads, 4x4 (i x o) accumulators per thread.
// Correlation structure: acc[i][j] += a[i] * e[i+j], e base = 4*(ty+tx).
// ---------------------------------------------------------------------------
#define TI 64
#define KC 64
#define QS_W 68      // padded row stride (16B-aligned vector loads)
#define ES_W 132

__global__ __launch_bounds__(256)
void band_kernel(const float* __restrict__ emb)
{
    __shared__ float Qs[KC][QS_W];    // [kk][ii]   64x68x4  = 17.4 KB
    __shared__ float Es[KC][ES_W];    // [kk][row]  64x132x4 = 33.8 KB

    const int tid = threadIdx.x;
    const int tx = tid & 15;
    const int ty = tid >> 4;
    const int i0 = blockIdx.x * TI;

    float acc[4][4];
    #pragma unroll
    for (int i = 0; i < 4; i++)
        #pragma unroll
        for (int j = 0; j < 4; j++) acc[i][j] = 0.f;

    for (int d0 = 0; d0 < D_DIM; d0 += KC) {
        // Load Qall tile: 64 rows x 64 cols = 1024 float4 (4/thread), transposed
        #pragma unroll
        for (int l = 0; l < 4; l++) {
            int idx = tid + l * 256;
            int row = idx >> 4;          // 0..63
            int c4  = idx & 15;          // 0..15
            float4 v = *reinterpret_cast<const float4*>(
                &g_Qall[(size_t)(i0 + row) * D_DIM + d0 + c4 * 4]);
            Qs[c4 * 4 + 0][row] = v.x;
            Qs[c4 * 4 + 1][row] = v.y;
            Qs[c4 * 4 + 2][row] = v.z;
            Qs[c4 * 4 + 3][row] = v.w;
        }
        // Load emb tile: 128 rows (clamped) x 64 cols = 2048 float4 (8/thread)
        #pragma unroll
        for (int l = 0; l < 8; l++) {
            int idx = tid + l * 256;
            int row = idx >> 4;          // 0..127
            int c4  = idx & 15;
            int r = i0 - 31 + row;
            r = min(max(r, 0), T_TOK - 1);   // clamped rows are never consumed
            float4 v = *reinterpret_cast<const float4*>(
                &emb[(size_t)r * D_DIM + d0 + c4 * 4]);
            Es[c4 * 4 + 0][row] = v.x;
            Es[c4 * 4 + 1][row] = v.y;
            Es[c4 * 4 + 2][row] = v.z;
            Es[c4 * 4 + 3][row] = v.w;
        }
        __syncthreads();

        const int ebase = ty * 4 + tx * 4;      // 16B-aligned in Es row
        #pragma unroll
        for (int kk = 0; kk < KC; kk++) {
            float4 av = *reinterpret_cast<const float4*>(&Qs[kk][ty * 4]);
            float4 e0 = *reinterpret_cast<const float4*>(&Es[kk][ebase]);
            float4 e1 = *reinterpret_cast<const float4*>(&Es[kk][ebase + 4]);
            float a[4] = {av.x, av.y, av.z, av.w};
            float e[8] = {e0.x, e0.y, e0.z, e0.w, e1.x, e1.y, e1.z, e1.w};
            #pragma unroll
            for (int i = 0; i < 4; i++)
                #pragma unroll
                for (int j = 0; j < 4; j++)
                    acc[i][j] = fmaf(a[i], e[i + j], acc[i][j]);
        }
        __syncthreads();
    }

    // Write band: M[i0+ty*4+i][tx*4 + 0..3]
    #pragma unroll
    for (int i = 0; i < 4; i++) {
        float4 v = make_float4(acc[i][0], acc[i][1], acc[i][2], acc[i][3]);
        *reinterpret_cast<float4*>(
            &g_M[(size_t)(i0 + ty * 4 + i) * BANDW + tx * 4]) = v;
    }
}

// ---------------------------------------------------------------------------
// Kernel 3: one warp per span. Scores come from the band (no dot products).
//   for q: s[k] = M[start+q][k - q + 31]; softmax; csum[k] += w
//   out[n] = sum_k csum[k] * emb[start+k]
// ---------------------------------------------------------------------------
__global__ __launch_bounds__(256)
void span_out_kernel(const float* __restrict__ emb,
                     const int*   __restrict__ spans,
                     float*       __restrict__ out,
                     int n)
{
    const int warp = (blockIdx.x * blockDim.x + threadIdx.x) >> 5;
    const int lane = threadIdx.x & 31;
    if (warp >= n) return;

    const int start = spans[2 * warp];
    const int L     = spans[2 * warp + 1] - start + 1;

    float csum = 0.f;                      // lane k holds column sum
    for (int q = 0; q < L; q++) {
        float s = (lane < L)
            ? g_M[(size_t)(start + q) * BANDW + (lane - q + 31)]
            : -INFINITY;
        float m = s;
        #pragma unroll
        for (int o = 16; o > 0; o >>= 1) m = fmaxf(m, __shfl_xor_sync(0xffffffffu, m, o));
        float e = (lane < L) ? __expf(s - m) : 0.f;
        float sum = e;
        #pragma unroll
        for (int o = 16; o > 0; o >>= 1) sum += __shfl_xor_sync(0xffffffffu, sum, o);
        csum += e / sum;
    }

    // Epilogue: out = csum @ E   (two 32-wide d-chunks in flight for MLP)
    const float* eb = emb + (size_t)start * D_DIM;
    float* od = out + (size_t)warp * D_DIM;
    for (int db = 0; db < D_DIM; db += 64) {
        float acc0 = 0.f, acc1 = 0.f;
        for (int k = 0; k < L; k++) {
            float c = __shfl_sync(0xffffffffu, csum, k);
            const float* er = eb + (size_t)k * D_DIM + db;
            acc0 = fmaf(c, er[lane], acc0);
            acc1 = fmaf(c, er[lane + 32], acc1);
        }
        od[db + lane]      = acc0;
        od[db + lane + 32] = acc1;
    }
}

// ---------------------------------------------------------------------------
extern "C" void kernel_launch(void* const* d_in, const int* in_sizes, int n_in,
                              void* d_out, int out_size)
{
    const float* emb   = (const float*)d_in[0];
    const int*   spans = (const int*)  d_in[1];
    const float* Wq    = (const float*)d_in[2];
    const float* bq    = (const float*)d_in[3];
    float* out = (float*)d_out;

    const int n_spans = in_sizes[1] / 2;

    dim3 g1(D_DIM / BN, T_TOK / BM);
    qproj_kernel<<<g1, 256>>>(emb, Wq, bq);

    band_kernel<<<T_TOK / TI, 256>>>(emb);

    const int blocks = (n_spans * 32 + 255) / 256;
    span_out_kernel<<<blocks, 256>>>(emb, spans, out, n_spans);
}

// round 13
// speedup vs baseline: 2.7752x; 1.5307x over previous
#include <cuda_runtime.h>
#include <cuda_bf16.h>
#include <math.h>
#include <stdint.h>

#define T_TOK 8192
#define D_DIM 768
#define W_MAX 32
#define BANDW 64

// Scratch
__device__ float g_Qall[(size_t)T_TOK * D_DIM];            // 25 MB
__device__ float g_M[(size_t)T_TOK * BANDW];               // 2 MB
__device__ __nv_bfloat16 g_Ahi[(size_t)T_TOK * D_DIM];     // 12.6 MB
__device__ __nv_bfloat16 g_Alo[(size_t)T_TOK * D_DIM];
__device__ __nv_bfloat16 g_Bhi[(size_t)D_DIM * D_DIM];     // 1.18 MB
__device__ __nv_bfloat16 g_Blo[(size_t)D_DIM * D_DIM];

// ---------------- PTX helpers (sm_80-era only: safe at compute_103) --------
__device__ __forceinline__ uint32_t smem_u32(const void* p) {
    uint32_t a;
    asm("{ .reg .u64 t; cvta.to.shared.u64 t, %1; cvt.u32.u64 %0, t; }" : "=r"(a) : "l"(p));
    return a;
}
__device__ __forceinline__ void ldm_x4(uint32_t* r, uint32_t addr) {
    asm volatile("ldmatrix.sync.aligned.m8n8.x4.shared.b16 {%0,%1,%2,%3}, [%4];"
                 : "=r"(r[0]), "=r"(r[1]), "=r"(r[2]), "=r"(r[3]) : "r"(addr));
}
__device__ __forceinline__ void mma_bf16(float* d, const uint32_t* a, const uint32_t* b) {
    asm volatile("mma.sync.aligned.m16n8k16.row.col.f32.bf16.bf16.f32 "
                 "{%0,%1,%2,%3},{%4,%5,%6,%7},{%8,%9},{%0,%1,%2,%3};"
                 : "+f"(d[0]), "+f"(d[1]), "+f"(d[2]), "+f"(d[3])
                 : "r"(a[0]), "r"(a[1]), "r"(a[2]), "r"(a[3]), "r"(b[0]), "r"(b[1]));
}
#define CP_ASYNC16(dst, src) \
    asm volatile("cp.async.cg.shared.global [%0], [%1], 16;" :: "r"(dst), "l"(src))
#define CP_COMMIT() asm volatile("cp.async.commit_group;" ::: "memory")
#define CP_WAIT1()  asm volatile("cp.async.wait_group 1;" ::: "memory")
#define CP_WAIT0()  asm volatile("cp.async.wait_group 0;" ::: "memory")

// ---------------------------------------------------------------------------
// Kernel A: fp32 -> (hi, lo) bf16 split, vectorized by 4.
// ---------------------------------------------------------------------------
__global__ void cvt_kernel(const float* __restrict__ src,
                           __nv_bfloat16* __restrict__ hi,
                           __nv_bfloat16* __restrict__ lo, int n4)
{
    int i = blockIdx.x * blockDim.x + threadIdx.x;
    if (i >= n4) return;
    float4 v = reinterpret_cast<const float4*>(src)[i];
    float f[4] = {v.x, v.y, v.z, v.w};
    __nv_bfloat16 h[4], l[4];
    #pragma unroll
    for (int j = 0; j < 4; j++) {
        h[j] = __float2bfloat16_rn(f[j]);
        l[j] = __float2bfloat16_rn(f[j] - __bfloat162float(h[j]));
    }
    reinterpret_cast<__nv_bfloat162*>(hi)[2 * i]     = __nv_bfloat162(h[0], h[1]);
    reinterpret_cast<__nv_bfloat162*>(hi)[2 * i + 1] = __nv_bfloat162(h[2], h[3]);
    reinterpret_cast<__nv_bfloat162*>(lo)[2 * i]     = __nv_bfloat162(l[0], l[1]);
    reinterpret_cast<__nv_bfloat162*>(lo)[2 * i + 1] = __nv_bfloat162(l[2], l[3]);
}

// ---------------------------------------------------------------------------
// Kernel B: split-bf16 GEMM via mma.sync (HMMA).  Q_all = 3 bf16 products + bias.
// CTA: 128x128 tile, 8 warps (2x4), warp tile 64x32, BK=32, cp.async 2-stage.
// ---------------------------------------------------------------------------
#define SA 40                    // smem row stride in bf16 (80 B: conflict-free)
#define BUF_ELT (128 * SA)

__global__ __launch_bounds__(256, 2)
void qproj_mma_kernel(const float* __restrict__ bias)
{
    __shared__ __nv_bfloat16 Asb[2][BUF_ELT];
    __shared__ __nv_bfloat16 Bsb[2][BUF_ELT];

    const int tid  = threadIdx.x;
    const int lane = tid & 31;
    const int w    = tid >> 5;
    const int i0 = blockIdx.x * 128;          // token rows
    const int n0 = blockIdx.y * 128;          // output cols
    const int mw = (w >> 2) * 64;
    const int nw = (w & 3) * 32;

    const uint32_t aS0 = smem_u32(&Asb[0][0]);
    const uint32_t bS0 = smem_u32(&Bsb[0][0]);

    // loader mapping: seg s = tid + j*256; row = s>>2 (0..127), seg-in-row = s&3
    const int lrow0 = tid >> 2;
    const int lseg  = tid & 3;

    // operand schedule: pass 0 hi*hi, 1 lo*hi, 2 hi*lo  (chunks of 24 each)
    const __nv_bfloat16* const Abase[3] = {g_Ahi, g_Alo, g_Ahi};
    const __nv_bfloat16* const Bbase[3] = {g_Bhi, g_Bhi, g_Blo};

    float acc[4][4][4];
    #pragma unroll
    for (int mi = 0; mi < 4; mi++)
        #pragma unroll
        for (int ni = 0; ni < 4; ni++)
            #pragma unroll
            for (int r = 0; r < 4; r++) acc[mi][ni][r] = 0.f;

    // preload bias pairs for this thread's columns
    float2 bia[4];
    #pragma unroll
    for (int ni = 0; ni < 4; ni++)
        bia[ni] = *reinterpret_cast<const float2*>(
            &bias[n0 + nw + ni * 8 + (lane & 3) * 2]);

    const int NCH = 72;   // 3 passes * 24 k-chunks

    // ---- issue chunk 0 ----
    {
        const __nv_bfloat16* Ap = Abase[0] + (size_t)(i0 + lrow0) * D_DIM;
        const __nv_bfloat16* Bp = Bbase[0] + (size_t)(n0 + lrow0) * D_DIM;
        const __nv_bfloat16* Ap2 = Abase[0] + (size_t)(i0 + lrow0 + 64) * D_DIM;
        const __nv_bfloat16* Bp2 = Bbase[0] + (size_t)(n0 + lrow0 + 64) * D_DIM;
        uint32_t da = aS0 + (lrow0 * SA + lseg * 8) * 2;
        uint32_t db = bS0 + (lrow0 * SA + lseg * 8) * 2;
        CP_ASYNC16(da, Ap + lseg * 8);
        CP_ASYNC16(db, Bp + lseg * 8);
        CP_ASYNC16(da + 64 * SA * 2, Ap2 + lseg * 8);
        CP_ASYNC16(db + 64 * SA * 2, Bp2 + lseg * 8);
        CP_COMMIT();
    }

    for (int c = 0; c < NCH; c++) {
        const int buf = c & 1;

        // ---- issue chunk c+1 into other buffer ----
        if (c + 1 < NCH) {
            const int p  = (c + 1) / 24;
            const int k0 = ((c + 1) % 24) * 32;
            const __nv_bfloat16* Ap = Abase[p] + (size_t)(i0 + lrow0) * D_DIM + k0 + lseg * 8;
            const __nv_bfloat16* Bp = Bbase[p] + (size_t)(n0 + lrow0) * D_DIM + k0 + lseg * 8;
            const __nv_bfloat16* Ap2 = Ap + (size_t)64 * D_DIM;
            const __nv_bfloat16* Bp2 = Bp + (size_t)64 * D_DIM;
            uint32_t da = aS0 + ((buf ^ 1) * BUF_ELT + lrow0 * SA + lseg * 8) * 2;
            uint32_t db = bS0 + ((buf ^ 1) * BUF_ELT + lrow0 * SA + lseg * 8) * 2;
            CP_ASYNC16(da, Ap);
            CP_ASYNC16(db, Bp);
            CP_ASYNC16(da + 64 * SA * 2, Ap2);
            CP_ASYNC16(db + 64 * SA * 2, Bp2);
            CP_COMMIT();
            CP_WAIT1();
        } else {
            CP_WAIT0();
        }
        __syncthreads();

        // ---- compute on buf ----
        const uint32_t aS = aS0 + buf * BUF_ELT * 2;
        const uint32_t bS = bS0 + buf * BUF_ELT * 2;
        #pragma unroll
        for (int ks = 0; ks < 32; ks += 16) {
            uint32_t afr[4][4];
            #pragma unroll
            for (int mi = 0; mi < 4; mi++) {
                int r = mw + mi * 16 + (lane & 15);
                uint32_t ad = aS + (r * SA + ks + (lane >> 4) * 8) * 2;
                ldm_x4(afr[mi], ad);
            }
            uint32_t bfr[4][2];
            #pragma unroll
            for (int nt = 0; nt < 4; nt += 2) {
                int g = lane >> 3;
                int row = nw + (nt + (g >> 1)) * 8 + (lane & 7);
                uint32_t bd = bS + (row * SA + ks + (g & 1) * 8) * 2;
                uint32_t t[4];
                ldm_x4(t, bd);
                bfr[nt][0] = t[0]; bfr[nt][1] = t[1];
                bfr[nt + 1][0] = t[2]; bfr[nt + 1][1] = t[3];
            }
            #pragma unroll
            for (int mi = 0; mi < 4; mi++)
                #pragma unroll
                for (int ni = 0; ni < 4; ni++)
                    mma_bf16(acc[mi][ni], afr[mi], bfr[ni]);
        }
        __syncthreads();
    }

    // ---- epilogue: direct float2 stores with bias ----
    #pragma unroll
    for (int mi = 0; mi < 4; mi++) {
        const int r0 = i0 + mw + mi * 16 + (lane >> 2);
        #pragma unroll
        for (int ni = 0; ni < 4; ni++) {
            const int gc = n0 + nw + ni * 8 + (lane & 3) * 2;
            float2 v0 = make_float2(acc[mi][ni][0] + bia[ni].x,
                                    acc[mi][ni][1] + bia[ni].y);
            float2 v1 = make_float2(acc[mi][ni][2] + bia[ni].x,
                                    acc[mi][ni][3] + bia[ni].y);
            *reinterpret_cast<float2*>(&g_Qall[(size_t)r0 * D_DIM + gc]) = v0;
            *reinterpret_cast<float2*>(&g_Qall[(size_t)(r0 + 8) * D_DIM + gc]) = v1;
        }
    }
}

// ---------------------------------------------------------------------------
// Kernel C: banded scores M[i][o] = Qall[i] . emb[i + o - 31]   (unchanged)
// ---------------------------------------------------------------------------
#define TI 64
#define KC 64
#define QS_W 68
#define ES_W 132

__global__ __launch_bounds__(256)
void band_kernel(const float* __restrict__ emb)
{
    __shared__ float Qs[KC][QS_W];
    __shared__ float Es[KC][ES_W];

    const int tid = threadIdx.x;
    const int tx = tid & 15;
    const int ty = tid >> 4;
    const int i0 = blockIdx.x * TI;

    float acc[4][4];
    #pragma unroll
    for (int i = 0; i < 4; i++)
        #pragma unroll
        for (int j = 0; j < 4; j++) acc[i][j] = 0.f;

    for (int d0 = 0; d0 < D_DIM; d0 += KC) {
        #pragma unroll
        for (int l = 0; l < 4; l++) {
            int idx = tid + l * 256;
            int row = idx >> 4;
            int c4  = idx & 15;
            float4 v = *reinterpret_cast<const float4*>(
                &g_Qall[(size_t)(i0 + row) * D_DIM + d0 + c4 * 4]);
            Qs[c4 * 4 + 0][row] = v.x;
            Qs[c4 * 4 + 1][row] = v.y;
            Qs[c4 * 4 + 2][row] = v.z;
            Qs[c4 * 4 + 3][row] = v.w;
        }
        #pragma unroll
        for (int l = 0; l < 8; l++) {
            int idx = tid + l * 256;
            int row = idx >> 4;
            int c4  = idx & 15;
            int r = i0 - 31 + row;
            r = min(max(r, 0), T_TOK - 1);
            float4 v = *reinterpret_cast<const float4*>(
                &emb[(size_t)r * D_DIM + d0 + c4 * 4]);
            Es[c4 * 4 + 0][row] = v.x;
            Es[c4 * 4 + 1][row] = v.y;
            Es[c4 * 4 + 2][row] = v.z;
            Es[c4 * 4 + 3][row] = v.w;
        }
        __syncthreads();

        const int ebase = ty * 4 + tx * 4;
        #pragma unroll
        for (int kk = 0; kk < KC; kk++) {
            float4 av = *reinterpret_cast<const float4*>(&Qs[kk][ty * 4]);
            float4 e0 = *reinterpret_cast<const float4*>(&Es[kk][ebase]);
            float4 e1 = *reinterpret_cast<const float4*>(&Es[kk][ebase + 4]);
            float a[4] = {av.x, av.y, av.z, av.w};
            float e[8] = {e0.x, e0.y, e0.z, e0.w, e1.x, e1.y, e1.z, e1.w};
            #pragma unroll
            for (int i = 0; i < 4; i++)
                #pragma unroll
                for (int j = 0; j < 4; j++)
                    acc[i][j] = fmaf(a[i], e[i + j], acc[i][j]);
        }
        __syncthreads();
    }

    #pragma unroll
    for (int i = 0; i < 4; i++) {
        float4 v = make_float4(acc[i][0], acc[i][1], acc[i][2], acc[i][3]);
        *reinterpret_cast<float4*>(
            &g_M[(size_t)(i0 + ty * 4 + i) * BANDW + tx * 4]) = v;
    }
}

// ---------------------------------------------------------------------------
// Kernel D: one warp per span (unchanged)
// ---------------------------------------------------------------------------
__global__ __launch_bounds__(256)
void span_out_kernel(const float* __restrict__ emb,
                     const int*   __restrict__ spans,
                     float*       __restrict__ out,
                     int n)
{
    const int warp = (blockIdx.x * blockDim.x + threadIdx.x) >> 5;
    const int lane = threadIdx.x & 31;
    if (warp >= n) return;

    const int start = spans[2 * warp];
    const int L     = spans[2 * warp + 1] - start + 1;

    float csum = 0.f;
    for (int q = 0; q < L; q++) {
        float s = (lane < L)
            ? g_M[(size_t)(start + q) * BANDW + (lane - q + 31)]
            : -INFINITY;
        float m = s;
        #pragma unroll
        for (int o = 16; o > 0; o >>= 1) m = fmaxf(m, __shfl_xor_sync(0xffffffffu, m, o));
        float e = (lane < L) ? __expf(s - m) : 0.f;
        float sum = e;
        #pragma unroll
        for (int o = 16; o > 0; o >>= 1) sum += __shfl_xor_sync(0xffffffffu, sum, o);
        csum += e / sum;
    }

    const float* eb = emb + (size_t)start * D_DIM;
    float* od = out + (size_t)warp * D_DIM;
    for (int db = 0; db < D_DIM; db += 64) {
        float acc0 = 0.f, acc1 = 0.f;
        for (int k = 0; k < L; k++) {
            float c = __shfl_sync(0xffffffffu, csum, k);
            const float* er = eb + (size_t)k * D_DIM + db;
            acc0 = fmaf(c, er[lane], acc0);
            acc1 = fmaf(c, er[lane + 32], acc1);
        }
        od[db + lane]      = acc0;
        od[db + lane + 32] = acc1;
    }
}

// ---------------------------------------------------------------------------
extern "C" void kernel_launch(void* const* d_in, const int* in_sizes, int n_in,
                              void* d_out, int out_size)
{
    const float* emb   = (const float*)d_in[0];
    const int*   spans = (const int*)  d_in[1];
    const float* Wq    = (const float*)d_in[2];
    const float* bq    = (const float*)d_in[3];
    float* out = (float*)d_out;

    const int n_spans = in_sizes[1] / 2;

    __nv_bfloat16 *ahi, *alo, *bhi, *blo;
    cudaGetSymbolAddress((void**)&ahi, g_Ahi);
    cudaGetSymbolAddress((void**)&alo, g_Alo);
    cudaGetSymbolAddress((void**)&bhi, g_Bhi);
    cudaGetSymbolAddress((void**)&blo, g_Blo);

    const int nA4 = T_TOK * D_DIM / 4;
    const int nB4 = D_DIM * D_DIM / 4;
    cvt_kernel<<<(nA4 + 255) / 256, 256>>>(emb, ahi, alo, nA4);
    cvt_kernel<<<(nB4 + 255) / 256, 256>>>(Wq, bhi, blo, nB4);

    dim3 gq(T_TOK / 128, D_DIM / 128);
    qproj_mma_kernel<<<gq, 256>>>(bq);

    band_kernel<<<T_TOK / TI, 256>>>(emb);

    const int blocks = (n_spans * 32 + 255) / 256;
    span_out_kernel<<<blocks, 256>>>(emb, spans, out, n_spans);
}